// round 10
// baseline (speedup 1.0000x reference)
#include <cuda_runtime.h>
#include <cuda_fp16.h>
#include <cstdint>

// Spatial RNN, 4 dirs, R=8 steps, C=64. f16 mma.sync (f16 accum) + LDSM/STSM.
// x:(8,192,192,64) fp32; W_*:(64,64); out:(8,192,192,256)
//
// One CTA per scan line (3072 CTAs x 192 thr, 6 warps). Warp tile m32 x n64:
// each warp owns 32 distinct rows, all 64 cols -> NO A-fragment duplication.
// 2 dirs x 8 chained [192,64]x[64,64] GEMMs. Packed f16x2 accumulators ->
// ~150 regs -> 2 CTAs/SM. Buffers: Xb (persistent f16 x) + P0/P1 ping-pong,
// 144B stride, zero guard rows, shift folded into LDSM addresses.

#define STRB 144                 // bytes per buffer row (64 f16 + pad)
#define BROWS 194                // rows 0..193, guards at 0 and 193
#define BUFB (BROWS * STRB)      // 27936 bytes
#define SMEM_DYN (3 * BUFB + 64) // 83872

static __device__ __forceinline__ uint32_t smem_u32(const void* p) {
    uint32_t a;
    asm("{ .reg .u64 t; cvta.to.shared.u64 t, %1; cvt.u32.u64 %0, t; }" : "=r"(a) : "l"(p));
    return a;
}
static __device__ __forceinline__ uint32_t pkh2(float lo, float hi) {
    uint32_t r;
    asm("cvt.rn.f16x2.f32 %0, %1, %2;" : "=r"(r) : "f"(hi), "f"(lo));
    return r;
}
static __device__ __forceinline__ uint32_t hmax2z(uint32_t v) {
    uint32_t r;
    asm("max.f16x2 %0, %1, %2;" : "=r"(r) : "r"(v), "r"(0u));
    return r;
}
static __device__ __forceinline__ uint32_t hadd2(uint32_t a, uint32_t b) {
    uint32_t r;
    asm("add.f16x2 %0, %1, %2;" : "=r"(r) : "r"(a), "r"(b));
    return r;
}
static __device__ __forceinline__ void unpkh2(uint32_t v, float& lo, float& hi) {
    asm("{ .reg .f16 l, h; mov.b32 {l, h}, %2; cvt.f32.f16 %0, l; cvt.f32.f16 %1, h; }"
        : "=f"(lo), "=f"(hi) : "r"(v));
}
static __device__ __forceinline__ void ldsm4(uint32_t a[4], uint32_t addr) {
    asm volatile("ldmatrix.sync.aligned.m8n8.x4.shared.b16 {%0,%1,%2,%3}, [%4];"
                 : "=r"(a[0]), "=r"(a[1]), "=r"(a[2]), "=r"(a[3]) : "r"(addr));
}
static __device__ __forceinline__ void stsm4(uint32_t addr, uint32_t r0, uint32_t r1,
                                             uint32_t r2, uint32_t r3) {
    asm volatile("stmatrix.sync.aligned.m8n8.x4.shared.b16 [%0], {%1,%2,%3,%4};"
                 :: "r"(addr), "r"(r0), "r"(r1), "r"(r2), "r"(r3) : "memory");
}
static __device__ __forceinline__ void mma16816h(uint32_t c[2], const uint32_t a[4],
                                                 const uint32_t b[2]) {
    asm volatile(
        "mma.sync.aligned.m16n8k16.row.col.f16.f16.f16.f16 "
        "{%0,%1}, {%2,%3,%4,%5}, {%6,%7}, {%0,%1};"
        : "+r"(c[0]), "+r"(c[1])
        : "r"(a[0]), "r"(a[1]), "r"(a[2]), "r"(a[3]), "r"(b[0]), "r"(b[1]));
}
static __device__ __forceinline__ void sts128(uint32_t addr, uint32_t a, uint32_t b,
                                              uint32_t c, uint32_t d) {
    asm volatile("st.shared.v4.b32 [%0], {%1,%2,%3,%4};"
                 :: "r"(addr), "r"(a), "r"(b), "r"(c), "r"(d) : "memory");
}

extern "C" __global__ void __launch_bounds__(192, 2)
rnn_kernel(const float* __restrict__ x,
           const float* __restrict__ W_left, const float* __restrict__ W_right,
           const float* __restrict__ W_up,   const float* __restrict__ W_down,
           float* __restrict__ out)
{
    extern __shared__ char dsm[];
    const uint32_t base = (smem_u32(dsm) + 15u) & ~15u;
    const uint32_t Xb = base;              // persistent f16 x
    const uint32_t P0 = base + BUFB;       // ping-pong state
    const uint32_t P1 = base + 2 * BUFB;

    const int tid  = threadIdx.x;
    const int lane = tid & 31;
    const int warp = tid >> 5;             // 0..5 = m-group of 32 rows
    const int gID  = lane >> 2;
    const int tg   = lane & 3;
    const int m0   = warp * 32;

    // --- geometry ---
    long inBase, outBase;
    int pixIn, pixOut, chBase;
    const float *Wfp, *Wbp;
    {
        int l = blockIdx.x;
        if (l < 1536) {                            // horizontal row
            inBase  = (long)l * (192 * 64);
            outBase = (long)l * (192 * 256);
            pixIn = 64;  pixOut = 256;  chBase = 0;
            Wfp = W_left;  Wbp = W_right;
        } else {                                    // vertical column
            int l2 = l - 1536;
            int b = l2 / 192, w = l2 % 192;
            inBase  = (long)b * (192 * 192 * 64)  + (long)w * 64;
            outBase = (long)b * (192 * 192 * 256) + (long)w * 256;
            pixIn = 192 * 64;  pixOut = 192 * 256;  chBase = 128;
            Wfp = W_up;  Wbp = W_down;
        }
    }
    const float* xl = x + inBase;
    float* ol = out + outBase;

    // --- zero guard rows (rows 0 and 193 of all three buffers) ---
    if (tid < 36) {
        asm volatile("st.shared.b32 [%0], %1;" :: "r"(Xb + tid * 4), "r"(0) : "memory");
        asm volatile("st.shared.b32 [%0], %1;" :: "r"(Xb + 193 * STRB + tid * 4), "r"(0) : "memory");
        asm volatile("st.shared.b32 [%0], %1;" :: "r"(P0 + tid * 4), "r"(0) : "memory");
        asm volatile("st.shared.b32 [%0], %1;" :: "r"(P0 + 193 * STRB + tid * 4), "r"(0) : "memory");
        asm volatile("st.shared.b32 [%0], %1;" :: "r"(P1 + tid * 4), "r"(0) : "memory");
        asm volatile("st.shared.b32 [%0], %1;" :: "r"(P1 + 193 * STRB + tid * 4), "r"(0) : "memory");
    }

    // --- load x (f16) into Xb rows 1..192 (once; both dirs start here) ---
    #pragma unroll
    for (int p = 0; p < 4; p++) {
        int i = tid + p * 192;                  // 0..767
        int r = i >> 2;
        int c0 = (i & 3) * 16;
        const float* xp = xl + (long)r * pixIn + c0;
        uint32_t h[8];
        #pragma unroll
        for (int j = 0; j < 4; j++) {
            float4 v = *reinterpret_cast<const float4*>(xp + j * 4);
            h[2 * j]     = pkh2(v.x, v.y);
            h[2 * j + 1] = pkh2(v.z, v.w);
        }
        uint32_t a0 = Xb + (r + 1) * STRB + c0 * 2;
        sts128(a0,      h[0], h[1], h[2], h[3]);
        sts128(a0 + 16, h[4], h[5], h[6], h[7]);
    }

    // LDSM/STSM per-thread row/col decomposition
    const int lrow = (lane & 7) + ((lane >> 3) & 1) * 8;
    const int lcol = (lane >> 4) * 16;
    const uint32_t stOff = (uint32_t)((m0 + lrow + 1) * STRB + lcol);

    __syncthreads();

    #pragma unroll 1
    for (int dir = 0; dir < 2; dir++) {
        const float* Wg = dir ? Wbp : Wfp;
        const int shift = dir ? 1 : -1;            // fwd reads r-1, bwd reads r+1

        // --- B fragments in registers (f16x2), from gmem (L2-hot) ---
        uint32_t b[4][8][2];
        #pragma unroll
        for (int kc = 0; kc < 4; kc++)
            #pragma unroll
            for (int nt = 0; nt < 8; nt++) {
                int k0 = kc * 16 + 2 * tg;
                int n  = nt * 8 + gID;
                b[kc][nt][0] = pkh2(__ldg(&Wg[(k0)     * 64 + n]), __ldg(&Wg[(k0 + 1) * 64 + n]));
                b[kc][nt][1] = pkh2(__ldg(&Wg[(k0 + 8) * 64 + n]), __ldg(&Wg[(k0 + 9) * 64 + n]));
            }

        uint32_t acc[2][8][2];                     // packed f16x2 accumulators
        #pragma unroll
        for (int mt = 0; mt < 2; mt++)
            #pragma unroll
            for (int nt = 0; nt < 8; nt++) {
                acc[mt][nt][0] = 0u;  acc[mt][nt][1] = 0u;
            }

        const uint32_t ldOff = (uint32_t)((m0 + lrow + shift + 1) * STRB + lcol);

        uint32_t src = Xb, dst = P0;

        #pragma unroll 1
        for (int s = 0; s < 8; s++) {
            const bool last = (s == 7);

            #pragma unroll
            for (int mt = 0; mt < 2; mt++) {
                uint32_t a[4][4];
                #pragma unroll
                for (int kc = 0; kc < 4; kc++)
                    ldsm4(a[kc], src + ldOff + mt * (16 * STRB) + kc * 32);

                uint32_t Cf[8][2];
                #pragma unroll
                for (int nt = 0; nt < 8; nt++) { Cf[nt][0] = 0u; Cf[nt][1] = 0u; }

                #pragma unroll
                for (int kc = 0; kc < 4; kc++)
                    #pragma unroll
                    for (int nt = 0; nt < 8; nt++)
                        mma16816h(Cf[nt], a[kc], b[kc][nt]);

                uint32_t h[8][2];
                #pragma unroll
                for (int nt = 0; nt < 8; nt++) {
                    h[nt][0] = hmax2z(Cf[nt][0]);       // relu (packed)
                    h[nt][1] = hmax2z(Cf[nt][1]);
                    acc[mt][nt][0] = hadd2(acc[mt][nt][0], h[nt][0]);
                    acc[mt][nt][1] = hadd2(acc[mt][nt][1], h[nt][1]);
                }
                if (!last) {
                    uint32_t sa = dst + stOff + mt * (16 * STRB);
                    #pragma unroll
                    for (int g = 0; g < 4; g++)
                        stsm4(sa + g * 32,
                              h[2 * g][0], h[2 * g][1], h[2 * g + 1][0], h[2 * g + 1][1]);
                }
            }

            if (!last) __syncthreads();
            src = dst;
            dst = (dst == P0) ? P1 : P0;
        }

        // --- epilogue: out = x + acc ---
        const int cb = chBase + dir * 64;
        #pragma unroll
        for (int mt = 0; mt < 2; mt++) {
            #pragma unroll
            for (int hh = 0; hh < 2; hh++) {
                int gr = m0 + mt * 16 + gID + hh * 8;
                const float* xp = xl + (long)gr * pixIn;
                float* op = ol + (long)gr * pixOut + cb;
                #pragma unroll
                for (int nt = 0; nt < 8; nt++) {
                    int col = nt * 8 + 2 * tg;
                    float a0, a1;
                    unpkh2(acc[mt][nt][hh], a0, a1);
                    float2 xv = *reinterpret_cast<const float2*>(xp + col);
                    float2 o = make_float2(xv.x + a0, xv.y + a1);
                    *reinterpret_cast<float2*>(op + col) = o;
                }
            }
        }
        __syncthreads();   // all P0/P1 reads done before next dir reuses them
    }
}

extern "C" void kernel_launch(void* const* d_in, const int* in_sizes, int n_in,
                              void* d_out, int out_size)
{
    const float* x  = (const float*)d_in[0];
    const float* wl = (const float*)d_in[1];
    const float* wr = (const float*)d_in[2];
    const float* wu = (const float*)d_in[3];
    const float* wd = (const float*)d_in[4];
    float* out = (float*)d_out;

    cudaFuncSetAttribute(rnn_kernel, cudaFuncAttributeMaxDynamicSharedMemorySize, SMEM_DYN);
    rnn_kernel<<<3072, 192, SMEM_DYN>>>(x, wl, wr, wu, wd, out);
}